// round 2
// baseline (speedup 1.0000x reference)
#include <cuda_runtime.h>
#include <math.h>

#define Tn 1024
#define Bn 512
#define CH 64      // chunk size
#define NCH 16     // number of chunks
#define Hn 20      // MLP hidden

// ---- device scratch (no allocations allowed) ----
__device__ float g_cw[1040];            // g_cw[d] = me[T-d] * dt  (d = 1..1024), g_cw[0] = 0
__device__ float g_Ihist[Tn * Bn];      // I history, row-major [time][batch]
__device__ float g_baseseg[8 * CH * Bn];// phase-A partial sums: [mseg][s][batch]
__device__ float g_state[3 * Bn];       // S,I,R planes

// ============================================================
// Kernel 0: MLP -> me, scaled+reversed into g_cw; init state,
// Ihist row 0, solution row 0, diff row T-1 (zeros).
// grid: 4 blocks x 256 threads (thread = one t row)
// ============================================================
__global__ void k_init(const float* __restrict__ t, const float* __restrict__ y,
                       const float* __restrict__ w1, const float* __restrict__ b1,
                       const float* __restrict__ w2, const float* __restrict__ b2,
                       const float* __restrict__ w3, const float* __restrict__ b3,
                       const float* __restrict__ w4, const float* __restrict__ b4,
                       float* __restrict__ out) {
    __shared__ float sw2[Hn * Hn], sw3[Hn * Hn];
    __shared__ float sw1[Hn], sb1[Hn], sb2[Hn], sb3[Hn], sw4[Hn];
    int tid = threadIdx.x;
    for (int i = tid; i < Hn * Hn; i += 256) { sw2[i] = w2[i]; sw3[i] = w3[i]; }
    if (tid < Hn) {
        sw1[tid] = w1[tid]; sb1[tid] = b1[tid];
        sb2[tid] = b2[tid]; sb3[tid] = b3[tid];
        sw4[tid] = w4[tid];
    }
    __syncthreads();

    int r = blockIdx.x * 256 + tid;          // 0..1023
    float dt = t[0] - t[1];
    float tv = t[r];

    float h1[Hn], h2[Hn];
#pragma unroll
    for (int j = 0; j < Hn; j++) h1[j] = tanhf(tv * sw1[j] + sb1[j]);
#pragma unroll
    for (int j = 0; j < Hn; j++) {
        float a = sb2[j];
#pragma unroll
        for (int i = 0; i < Hn; i++) a += h1[i] * sw2[i * Hn + j];
        h2[j] = tanhf(a);
    }
#pragma unroll
    for (int j = 0; j < Hn; j++) {
        float a = sb3[j];
#pragma unroll
        for (int i = 0; i < Hn; i++) a += h2[i] * sw3[i * Hn + j];
        h1[j] = tanhf(a);                    // reuse h1 as h3
    }
    float a = b4[0];
#pragma unroll
    for (int i = 0; i < Hn; i++) a += h1[i] * sw4[i];
    float me = 1.0f / (1.0f + expf(-a));

    g_cw[Tn - r] = me * dt;                  // cw[d] = me[T-d]*dt
    if (r == 0) g_cw[0] = 0.0f;

    if (r < Bn) {
        float S = y[r * 3 + 0], I = y[r * 3 + 1], R = y[r * 3 + 2];
        g_state[r] = S; g_state[Bn + r] = I; g_state[2 * Bn + r] = R;
        g_Ihist[r] = I;                      // Ihist[0][r]
        // solution[0][r][:] = y0
        float* so = out + (size_t)r * 3;
        so[0] = S; so[1] = I; so[2] = R;
        // diff[T-1][r][:] = 0
        float* df = out + (size_t)Tn * Bn * 3 + ((size_t)(Tn - 1) * Bn + r) * 3;
        df[0] = 0.0f; df[1] = 0.0f; df[2] = 0.0f;
    }
}

// ============================================================
// Phase A (chunk k >= 1): base[s][b] = sum_{m<k*CH} cw[kC+s-m] * Ihist[m][b]
// Split into 8 m-segments (separate output buffers -> deterministic, no atomics).
// grid: (2 sHalf, 8 btile, 8 mseg) = 128 blocks x 256 threads.
// Each thread: 8 consecutive s-outputs (register accs) x 1 batch.
// ============================================================
__global__ void __launch_bounds__(256) k_phaseA(int k) {
    __shared__ float cws[1024];
    for (int i = threadIdx.x; i < 1024; i += 256) cws[i] = g_cw[i];
    __syncthreads();

    const int M    = k * CH;
    const int tb   = threadIdx.x & 63;
    const int b    = blockIdx.y * 64 + tb;
    const int s0   = blockIdx.x * 32 + (threadIdx.x >> 6) * 8;
    const int mlen = M >> 3;                  // M/8, divisible (M = 64k)
    const int m0   = blockIdx.z * mlen;
    const int m1   = m0 + mlen;

    float acc[8] = {0, 0, 0, 0, 0, 0, 0, 0};
    const int cbase = M + s0;
    const float* Ip = g_Ihist + b;

#pragma unroll 4
    for (int m = m0; m < m1; m++) {
        float v = Ip[(size_t)m * Bn];
        const float* cp = &cws[cbase - m];
#pragma unroll
        for (int u = 0; u < 8; u++) acc[u] += v * cp[u];
    }

    float* op = g_baseseg + ((size_t)blockIdx.z * CH + s0) * Bn + b;
#pragma unroll
    for (int u = 0; u < 8; u++) op[(size_t)u * Bn] = acc[u];
}

// ============================================================
// Phase B (chunk k = 0..15): serial Euler steps for this chunk.
// grid: 16 blocks x 256 threads. Block owns 32 batches; warp 0 lane = batch.
// Preamble (256 threads): reduce the 8 base segments into smem, load cw.
// Serial loop: within-chunk triangle from thread-private smem columns.
// ============================================================
__global__ void __launch_bounds__(256) k_phaseB(const float* __restrict__ t,
                                                const float* __restrict__ beta_p,
                                                const float* __restrict__ gamma_p,
                                                float* __restrict__ out, int k) {
    __shared__ float cwB[CH];
    __shared__ float baseS[CH * 32];
    __shared__ float Iloc[CH * 32];

    const int tid = threadIdx.x;
    const int bb  = blockIdx.x * 32;

    if (tid < CH) cwB[tid] = g_cw[tid];

    for (int e = tid; e < CH * 32; e += 256) {
        int s = e >> 5, lane = e & 31;
        float v = 0.0f;
        if (k > 0) {
#pragma unroll
            for (int seg = 0; seg < 8; seg++)
                v += g_baseseg[((size_t)seg * CH + s) * Bn + bb + lane];
        }
        baseS[s * 32 + lane] = v;
    }
    if (k == 0 && tid < 32) Iloc[tid] = g_Ihist[bb + tid];   // Iloc[0] = I_0
    __syncthreads();

    if (tid < 32) {
        const int lane = tid;
        const int b = bb + lane;
        const float dt    = t[0] - t[1];
        const float beta  = beta_p[0];
        const float gamma = gamma_p[0];
        float S = g_state[b], I = g_state[Bn + b], R = g_state[2 * Bn + b];

        const int sbeg = (k == 0) ? 1 : 0;
        for (int s = sbeg; s < CH; s++) {
            float a0 = baseS[s * 32 + lane], a1 = 0.f, a2 = 0.f, a3 = 0.f;
            int d = 1;
            for (; d + 3 <= s; d += 4) {
                a0 += cwB[d + 0] * Iloc[(s - d - 0) * 32 + lane];
                a1 += cwB[d + 1] * Iloc[(s - d - 1) * 32 + lane];
                a2 += cwB[d + 2] * Iloc[(s - d - 2) * 32 + lane];
                a3 += cwB[d + 3] * Iloc[(s - d - 3) * 32 + lane];
            }
            for (; d <= s; d++) a0 += cwB[d] * Iloc[(s - d) * 32 + lane];
            float integro = (a0 + a1) + (a2 + a3);

            float bSI = beta * S * I;
            float dS = -bSI + integro;
            float dI = bSI - gamma * I;
            float dR = gamma * I - integro;
            S += dt * dS; I += dt * dI; R += dt * dR;

            const int j = k * CH + s;
            float* so = out + ((size_t)j * Bn + b) * 3;
            so[0] = S; so[1] = I; so[2] = R;
            float* df = out + (size_t)Tn * Bn * 3 + ((size_t)(j - 1) * Bn + b) * 3;
            df[0] = dS; df[1] = dI; df[2] = dR;

            g_Ihist[(size_t)j * Bn + b] = I;
            Iloc[s * 32 + lane] = I;
        }
        g_state[b] = S; g_state[Bn + b] = I; g_state[2 * Bn + b] = R;
    }
}

// ============================================================
// Launch: k_init, then alternating A(k)/B(k) chain (32 graph nodes).
// ============================================================
extern "C" void kernel_launch(void* const* d_in, const int* in_sizes, int n_in,
                              void* d_out, int out_size) {
    const float* t    = (const float*)d_in[0];
    const float* y    = (const float*)d_in[1];
    const float* w1   = (const float*)d_in[2];
    const float* b1   = (const float*)d_in[3];
    const float* w2   = (const float*)d_in[4];
    const float* b2   = (const float*)d_in[5];
    const float* w3   = (const float*)d_in[6];
    const float* b3   = (const float*)d_in[7];
    const float* w4   = (const float*)d_in[8];
    const float* b4   = (const float*)d_in[9];
    const float* beta = (const float*)d_in[10];
    const float* gamma= (const float*)d_in[11];
    float* out = (float*)d_out;

    k_init<<<4, 256>>>(t, y, w1, b1, w2, b2, w3, b3, w4, b4, out);
    k_phaseB<<<16, 256>>>(t, beta, gamma, out, 0);
    for (int k = 1; k < NCH; k++) {
        k_phaseA<<<dim3(2, 8, 8), 256>>>(k);
        k_phaseB<<<16, 256>>>(t, beta, gamma, out, k);
    }
}

// round 3
// speedup vs baseline: 2.2153x; 2.2153x over previous
#include <cuda_runtime.h>
#include <math.h>

#define Tn 1024
#define Bn 512
#define CH 64      // chunk size
#define NCH 16     // number of chunks
#define Hn 20      // MLP hidden

// ---- device scratch (no allocations allowed) ----
__device__ float g_cw[1040];             // g_cw[d] = me[T-d]*dt (d=1..1023), g_cw[0]=0
__device__ float g_Ihist[Tn * Bn];       // I history [time][batch]
__device__ float g_baseseg[8 * Bn * CH]; // phase-A partials: [seg][batch][s]  (transposed!)
__device__ float g_state[3 * Bn];        // S,I,R planes

// ============================================================
// Kernel 0: MLP -> cw; init state, Ihist row 0, solution row 0,
// diff row T-1 (zeros). grid: 4 x 256 (thread = t row)
// ============================================================
__global__ void k_init(const float* __restrict__ t, const float* __restrict__ y,
                       const float* __restrict__ w1, const float* __restrict__ b1,
                       const float* __restrict__ w2, const float* __restrict__ b2,
                       const float* __restrict__ w3, const float* __restrict__ b3,
                       const float* __restrict__ w4, const float* __restrict__ b4,
                       float* __restrict__ out) {
    __shared__ float sw2[Hn * Hn], sw3[Hn * Hn];
    __shared__ float sw1[Hn], sb1[Hn], sb2[Hn], sb3[Hn], sw4[Hn];
    int tid = threadIdx.x;
    for (int i = tid; i < Hn * Hn; i += 256) { sw2[i] = w2[i]; sw3[i] = w3[i]; }
    if (tid < Hn) {
        sw1[tid] = w1[tid]; sb1[tid] = b1[tid];
        sb2[tid] = b2[tid]; sb3[tid] = b3[tid];
        sw4[tid] = w4[tid];
    }
    __syncthreads();

    int r = blockIdx.x * 256 + tid;          // 0..1023
    float dt = t[0] - t[1];
    float tv = t[r];

    float h1[Hn], h2[Hn];
#pragma unroll
    for (int j = 0; j < Hn; j++) h1[j] = tanhf(tv * sw1[j] + sb1[j]);
#pragma unroll
    for (int j = 0; j < Hn; j++) {
        float a = sb2[j];
#pragma unroll
        for (int i = 0; i < Hn; i++) a += h1[i] * sw2[i * Hn + j];
        h2[j] = tanhf(a);
    }
#pragma unroll
    for (int j = 0; j < Hn; j++) {
        float a = sb3[j];
#pragma unroll
        for (int i = 0; i < Hn; i++) a += h2[i] * sw3[i * Hn + j];
        h1[j] = tanhf(a);                    // h3
    }
    float a = b4[0];
#pragma unroll
    for (int i = 0; i < Hn; i++) a += h1[i] * sw4[i];
    float me = 1.0f / (1.0f + expf(-a));

    g_cw[Tn - r] = me * dt;
    if (r == 0) g_cw[0] = 0.0f;

    if (r < Bn) {
        float S = y[r * 3 + 0], I = y[r * 3 + 1], R = y[r * 3 + 2];
        g_state[r] = S; g_state[Bn + r] = I; g_state[2 * Bn + r] = R;
        g_Ihist[r] = I;
        float* so = out + (size_t)r * 3;
        so[0] = S; so[1] = I; so[2] = R;
        float* df = out + (size_t)Tn * Bn * 3 + ((size_t)(Tn - 1) * Bn + r) * 3;
        df[0] = 0.0f; df[1] = 0.0f; df[2] = 0.0f;
    }
}

// ============================================================
// Phase A (chunk k>=1): base[s][b] = sum_{m<k*CH} cw[kCH+s-m]*Ihist[m][b]
// 8 m-segments -> disjoint buffers. grid (2,8,8) x 256.
// Output layout: g_baseseg[(seg*Bn + b)*CH + s]  (float4-friendly)
// ============================================================
__global__ void __launch_bounds__(256) k_phaseA(int k) {
    __shared__ float cws[1024];
    for (int i = threadIdx.x; i < 1024; i += 256) cws[i] = g_cw[i];
    __syncthreads();

    const int M    = k * CH;
    const int tb   = threadIdx.x & 63;
    const int b    = blockIdx.y * 64 + tb;
    const int s0   = blockIdx.x * 32 + (threadIdx.x >> 6) * 8;
    const int mlen = M >> 3;
    const int m0   = blockIdx.z * mlen;
    const int m1   = m0 + mlen;

    float acc[8] = {0, 0, 0, 0, 0, 0, 0, 0};
    const int cbase = M + s0;
    const float* Ip = g_Ihist + b;

#pragma unroll 4
    for (int m = m0; m < m1; m++) {
        float v = Ip[(size_t)m * Bn];
        const float* cp = &cws[cbase - m];
#pragma unroll
        for (int u = 0; u < 8; u++) acc[u] += v * cp[u];
    }

    float* op = g_baseseg + ((size_t)blockIdx.z * Bn + b) * CH + s0;
    float4* v4 = (float4*)op;
    v4[0] = make_float4(acc[0], acc[1], acc[2], acc[3]);
    v4[1] = make_float4(acc[4], acc[5], acc[6], acc[7]);
}

// ============================================================
// Phase B (systolic): 64 blocks x 256 threads; warp = 1 batch.
// Lane l owns chunk-steps l and l+32. Scatter-accumulate via shfl
// broadcast of I; all lanes carry S,I,R redundantly.
// ============================================================
__global__ void __launch_bounds__(256) k_phaseB(const float* __restrict__ t,
                                                const float* __restrict__ beta_p,
                                                const float* __restrict__ gamma_p,
                                                float* __restrict__ out, int k) {
    __shared__ float cwB[CH];

    const int tid  = threadIdx.x;
    const int wid  = tid >> 5;
    const int lane = tid & 31;
    const int b    = blockIdx.x * 8 + wid;

    if (tid < CH) cwB[tid] = g_cw[tid];
    __syncthreads();

    const float dt    = t[0] - t[1];
    const float beta  = beta_p[0];
    const float gamma = gamma_p[0];

    float S = g_state[b], I = g_state[Bn + b], R = g_state[2 * Bn + b];

    // accumulators for owned steps (seed with phase-A base)
    float acc0 = 0.0f, acc1 = 0.0f;
    if (k > 0) {
#pragma unroll
        for (int seg = 0; seg < 8; seg++) {
            const float* bp = g_baseseg + ((size_t)seg * Bn + b) * CH;
            acc0 += bp[lane];
            acc1 += bp[lane + 32];
        }
    }

    // per-lane saved outputs
    float svS0 = 0.f, svI0 = 0.f, svR0 = 0.f, svdS0 = 0.f, svdI0 = 0.f, svdR0 = 0.f;
    float svS1 = 0.f, svI1 = 0.f, svR1 = 0.f, svdS1 = 0.f, svdI1 = 0.f, svdR1 = 0.f;

    // ---- s = 0..31 : owner = lane s, accumulator acc0 ----
#pragma unroll 8
    for (int s = 0; s < 32; s++) {
        float integro = __shfl_sync(0xffffffffu, acc0, s);
        float I_bc;
        if (k == 0 && s == 0) {
            I_bc = I;                        // initial condition broadcast; no step
        } else {
            float bSI = beta * S * I;
            float dS = integro - bSI;
            float dI = bSI - gamma * I;
            float dR = gamma * I - integro;
            S += dt * dS; I += dt * dI; R += dt * dR;
            I_bc = I;
            bool own = (lane == s);
            svS0  = own ? S  : svS0;  svI0  = own ? I  : svI0;  svR0  = own ? R  : svR0;
            svdS0 = own ? dS : svdS0; svdI0 = own ? dI : svdI0; svdR0 = own ? dR : svdR0;
        }
        int d0 = lane - s;
        if (d0 > 0) acc0 += cwB[d0] * I_bc;
        acc1 += cwB[lane + 32 - s] * I_bc;   // always in (0,63]
    }

    // ---- s = 32..63 : owner = lane s-32, accumulator acc1 ----
#pragma unroll 8
    for (int s = 32; s < 64; s++) {
        float integro = __shfl_sync(0xffffffffu, acc1, s - 32);
        float bSI = beta * S * I;
        float dS = integro - bSI;
        float dI = bSI - gamma * I;
        float dR = gamma * I - integro;
        S += dt * dS; I += dt * dI; R += dt * dR;
        bool own = (lane == s - 32);
        svS1  = own ? S  : svS1;  svI1  = own ? I  : svI1;  svR1  = own ? R  : svR1;
        svdS1 = own ? dS : svdS1; svdI1 = own ? dI : svdI1; svdR1 = own ? dR : svdR1;
        int d1 = lane + 32 - s;
        if (d1 > 0) acc1 += cwB[d1] * I;
    }

    // ---- write-out: each lane stores its two steps ----
    float* diffb = out + (size_t)Tn * Bn * 3;

    int j0 = k * CH + lane;
    if (!(k == 0 && lane == 0)) {
        float* so = out + ((size_t)j0 * Bn + b) * 3;
        so[0] = svS0; so[1] = svI0; so[2] = svR0;
        float* df = diffb + ((size_t)(j0 - 1) * Bn + b) * 3;
        df[0] = svdS0; df[1] = svdI0; df[2] = svdR0;
        g_Ihist[(size_t)j0 * Bn + b] = svI0;
    }
    int j1 = j0 + 32;
    {
        float* so = out + ((size_t)j1 * Bn + b) * 3;
        so[0] = svS1; so[1] = svI1; so[2] = svR1;
        float* df = diffb + ((size_t)(j1 - 1) * Bn + b) * 3;
        df[0] = svdS1; df[1] = svdI1; df[2] = svdR1;
        g_Ihist[(size_t)j1 * Bn + b] = svI1;
    }

    // carry state to next chunk (all lanes agree; lane 31 writes)
    if (lane == 31) {
        g_state[b] = S; g_state[Bn + b] = I; g_state[2 * Bn + b] = R;
    }
}

// ============================================================
// Launch chain: init, then B(0), then A(k)/B(k) for k=1..15.
// ============================================================
extern "C" void kernel_launch(void* const* d_in, const int* in_sizes, int n_in,
                              void* d_out, int out_size) {
    const float* t    = (const float*)d_in[0];
    const float* y    = (const float*)d_in[1];
    const float* w1   = (const float*)d_in[2];
    const float* b1   = (const float*)d_in[3];
    const float* w2   = (const float*)d_in[4];
    const float* b2   = (const float*)d_in[5];
    const float* w3   = (const float*)d_in[6];
    const float* b3   = (const float*)d_in[7];
    const float* w4   = (const float*)d_in[8];
    const float* b4   = (const float*)d_in[9];
    const float* beta = (const float*)d_in[10];
    const float* gamma= (const float*)d_in[11];
    float* out = (float*)d_out;

    k_init<<<4, 256>>>(t, y, w1, b1, w2, b2, w3, b3, w4, b4, out);
    k_phaseB<<<64, 256>>>(t, beta, gamma, out, 0);
    for (int k = 1; k < NCH; k++) {
        k_phaseA<<<dim3(2, 8, 8), 256>>>(k);
        k_phaseB<<<64, 256>>>(t, beta, gamma, out, k);
    }
}

// round 4
// speedup vs baseline: 3.7092x; 1.6744x over previous
#include <cuda_runtime.h>
#include <math.h>

#define Tn 1024
#define Bn 512
#define CH 64
#define NCH 16
#define Hn 20
#define NB 128                       // grid blocks (all resident: 128 <= 148 SMs)
#define OUT_DIFF (Tn * Bn * 3)

// ---- device scratch (static, no allocations) ----
__device__ float g_cw[1024];                 // cw[d] = me[Tn-d]*dt, d in [1,1023]; cw[0]=0
__device__ float g_Ihist[Tn * Bn];           // I history [time][batch]
__device__ float g_baseA[2][16 * Bn * CH];   // A_old partials, dbl-buffered: [par][msl][b][s]
__device__ unsigned g_cnt;                   // barrier arrivals (returns to 0 each barrier)
__device__ unsigned g_gen;                   // barrier generation (monotonic across replays)

// ---------------- software grid barrier (all NB blocks resident) ----------------
__device__ __forceinline__ void gridbar() {
    __threadfence();                 // release this thread's prior global writes
    __syncthreads();
    if (threadIdx.x == 0) {
        volatile unsigned* genp = &g_gen;
        unsigned g = *genp;
        unsigned a = atomicAdd(&g_cnt, 1u);
        if (a == NB - 1u) {
            g_cnt = 0u;
            __threadfence();
            atomicAdd(&g_gen, 1u);
        } else {
            while (*genp == g) { }
        }
        __threadfence();
    }
    __syncthreads();
}

// ---------------- B chunk: serial Euler steps, warp-systolic, branch-free ----------------
// Lane owns chunk-steps lane and lane+32. All lanes carry S,I,R redundantly.
template <int FIRST>
__device__ __forceinline__ void chunkB(int k, int b, int wid, int lane,
                                       float& S, float& I, float& R,
                                       float dtv, float beta, float gamma,
                                       const float* __restrict__ cwS,
                                       float (*smemI)[CH],
                                       float* __restrict__ out) {
    float acc0 = 0.0f, acc1 = 0.0f;

    if (!FIRST) {
        // recent contribution: previous chunk's I values from warp-private smem stash
#pragma unroll 8
        for (int m = 0; m < CH; m++) {
            float Iv = smemI[wid][m];
            acc0 += cwS[96  + lane - m] * Iv;   // d = 64 + lane - m  in [1,95]
            acc1 += cwS[128 + lane - m] * Iv;   // d = 96 + lane - m  in [33,127]
        }
        if (k >= 2) {
            // old-history partials (computed by A-warps during previous chunk)
            const float* base = g_baseA[k & 1];
#pragma unroll
            for (int msl = 0; msl < 16; msl++) {
                const float* p = base + ((size_t)msl * Bn + b) * CH;
                acc0 += __ldcg(p + lane);
                acc1 += __ldcg(p + lane + 32);
            }
        }
    }

    float svS0 = 0.f, svI0 = 0.f, svR0 = 0.f, svdS0 = 0.f, svdI0 = 0.f, svdR0 = 0.f;
    float svS1 = 0.f, svI1 = 0.f, svR1 = 0.f, svdS1 = 0.f, svdI1 = 0.f, svdR1 = 0.f;

    if (FIRST) {
        svI0 = I;                               // lane 0 keeps I_0 for the smem stash
        acc0 += cwS[32 + lane] * I;             // I_0 contribution, d = lane   (cw[0]=0)
        acc1 += cwS[64 + lane] * I;             // d = lane + 32
    }

    // ---- steps s = (FIRST?1:0)..31, accumulator acc0 ----
#pragma unroll
    for (int s = FIRST ? 1 : 0; s < 32; s++) {
        float integro = __shfl_sync(0xffffffffu, acc0, s);
        float bSI = beta * S * I;
        float dS = integro - bSI;
        float dI = bSI - gamma * I;
        float dR = gamma * I - integro;
        S = fmaf(dtv, dS, S); I = fmaf(dtv, dI, I); R = fmaf(dtv, dR, R);
        bool own = (lane == s);
        svS0  = own ? S  : svS0;  svI0  = own ? I  : svI0;  svR0  = own ? R  : svR0;
        svdS0 = own ? dS : svdS0; svdI0 = own ? dI : svdI0; svdR0 = own ? dR : svdR0;
        acc0 += cwS[32 + lane - s] * I;         // d = lane - s   (pad zeros for lane<=s)
        acc1 += cwS[64 + lane - s] * I;         // d = lane+32-s  in [1,63]
    }

    // ---- steps 32..63, accumulator acc1 ----
#pragma unroll
    for (int s2 = 0; s2 < 32; s2++) {
        float integro = __shfl_sync(0xffffffffu, acc1, s2);
        float bSI = beta * S * I;
        float dS = integro - bSI;
        float dI = bSI - gamma * I;
        float dR = gamma * I - integro;
        S = fmaf(dtv, dS, S); I = fmaf(dtv, dI, I); R = fmaf(dtv, dR, R);
        bool own = (lane == s2);
        svS1  = own ? S  : svS1;  svI1  = own ? I  : svI1;  svR1  = own ? R  : svR1;
        svdS1 = own ? dS : svdS1; svdI1 = own ? dI : svdI1; svdR1 = own ? dR : svdR1;
        acc1 += cwS[32 + lane - s2] * I;        // d = (lane+32)-(s2+32)
    }

    // ---- write-out ----
    float* diffb = out + OUT_DIFF;
    int j0 = k * CH + lane;
    if (!(FIRST && lane == 0)) {                // j=0 row handled by init
        float* so = out + ((size_t)j0 * Bn + b) * 3;
        so[0] = svS0; so[1] = svI0; so[2] = svR0;
        float* df = diffb + ((size_t)(j0 - 1) * Bn + b) * 3;
        df[0] = svdS0; df[1] = svdI0; df[2] = svdR0;
        g_Ihist[(size_t)j0 * Bn + b] = svI0;
    }
    int j1 = j0 + 32;
    {
        float* so = out + ((size_t)j1 * Bn + b) * 3;
        so[0] = svS1; so[1] = svI1; so[2] = svR1;
        float* df = diffb + ((size_t)(j1 - 1) * Bn + b) * 3;
        df[0] = svdS1; df[1] = svdI1; df[2] = svdR1;
        g_Ihist[(size_t)j1 * Bn + b] = svI1;
    }
    // stash this chunk's I values for next chunk's recent-loop (warp-private)
    smemI[wid][lane]      = svI0;
    smemI[wid][lane + 32] = svI1;
}

// ---------------- A_old: history partials for target chunk K, m < 64*(K-1) ----------------
// 512 A-warps: W = btile(16) | msl(16) | stile(2). Warp: 32 b (lanes) x 32 s (regs).
__device__ __forceinline__ void do_A_old(int K, int W, int lane,
                                         const float* __restrict__ cwS) {
    const int btile = W & 15;
    const int b     = btile * 32 + lane;
    const int rest  = W >> 4;
    const int msl   = rest & 15;
    const int s0w   = (rest >> 4) * 32;
    const int Mold  = 64 * (K - 1);
    const int len   = Mold >> 4;               // divisible: Mold = 64(K-1)
    const int m0    = msl * len;

    float acc[32];
#pragma unroll
    for (int s = 0; s < 32; s++) acc[s] = 0.0f;

    const float* cwb = cwS + 32 + 64 * K + s0w;
#pragma unroll 2
    for (int m = m0; m < m0 + len; m++) {
        float v = __ldcg(&g_Ihist[(size_t)m * Bn + b]);
        const float* cp = cwb - m;             // cp[s] = cw[64K + s0w + s - m] (smem bcast)
#pragma unroll
        for (int s = 0; s < 32; s++) acc[s] = fmaf(cp[s], v, acc[s]);
    }

    float4* dst = (float4*)(&g_baseA[K & 1][((size_t)msl * Bn + b) * CH + s0w]);
#pragma unroll
    for (int q = 0; q < 8; q++)
        dst[q] = make_float4(acc[4 * q], acc[4 * q + 1], acc[4 * q + 2], acc[4 * q + 3]);
}

// ---------------- the single persistent kernel ----------------
__global__ void __launch_bounds__(256, 1)
mega(const float* __restrict__ t,  const float* __restrict__ y,
     const float* __restrict__ w1, const float* __restrict__ b1,
     const float* __restrict__ w2, const float* __restrict__ b2,
     const float* __restrict__ w3, const float* __restrict__ b3,
     const float* __restrict__ w4, const float* __restrict__ b4,
     const float* __restrict__ beta_p, const float* __restrict__ gamma_p,
     float* __restrict__ out) {
    __shared__ float cwS[1056];                // [0..31]=0, [32+d]=cw[d] for d in [0,1023]
    __shared__ float smemI[4][CH];             // per-B-warp I stash of previous chunk

    const int tid  = threadIdx.x;
    const int blk  = blockIdx.x;
    const int wid  = tid >> 5;
    const int lane = tid & 31;
    const int gtid = blk * 256 + tid;

    const float dtv   = t[0] - t[1];
    const float beta  = beta_p[0];
    const float gamma = gamma_p[0];

    // ================= init: MLP -> g_cw; output row 0 / diff row Tn-1 =================
    if (gtid < Tn) {
        const int r = gtid;
        float tv = t[r];
        float h1[Hn], h2[Hn];
#pragma unroll
        for (int j = 0; j < Hn; j++) h1[j] = tanhf(tv * __ldg(w1 + j) + __ldg(b1 + j));
#pragma unroll
        for (int j = 0; j < Hn; j++) {
            float a = __ldg(b2 + j);
#pragma unroll
            for (int i = 0; i < Hn; i++) a += h1[i] * __ldg(w2 + i * Hn + j);
            h2[j] = tanhf(a);
        }
#pragma unroll
        for (int j = 0; j < Hn; j++) {
            float a = __ldg(b3 + j);
#pragma unroll
            for (int i = 0; i < Hn; i++) a += h2[i] * __ldg(w3 + i * Hn + j);
            h1[j] = tanhf(a);                  // h3
        }
        float a = __ldg(b4);
#pragma unroll
        for (int i = 0; i < Hn; i++) a += h1[i] * __ldg(w4 + i);
        float me = 1.0f / (1.0f + expf(-a));

        if (r > 0) g_cw[Tn - r] = me * dtv;
        else       g_cw[0] = 0.0f;

        if (r < Bn) {
            float S0 = y[r * 3 + 0], I0 = y[r * 3 + 1], R0 = y[r * 3 + 2];
            g_Ihist[r] = I0;
            float* so = out + (size_t)r * 3;
            so[0] = S0; so[1] = I0; so[2] = R0;
            float* df = out + OUT_DIFF + ((size_t)(Tn - 1) * Bn + r) * 3;
            df[0] = 0.0f; df[1] = 0.0f; df[2] = 0.0f;
        }
    }
    gridbar();                                  // cw + row0 visible chip-wide

    // load cw into smem with 32-zero pad (once, persists across all chunks)
    for (int i = tid; i < 1056; i += 256)
        cwS[i] = (i < 32) ? 0.0f : g_cw[i - 32];
    __syncthreads();

    // B-warp persistent state
    const int b = blk * 4 + wid;                // valid for wid < 4
    float S = 0.f, I = 0.f, R = 0.f;
    if (wid < 4) { S = y[b * 3 + 0]; I = y[b * 3 + 1]; R = y[b * 3 + 2]; }

    const int W = blk * 4 + (wid - 4);          // A-warp id, valid for wid >= 4

    // ================= chunk loop =================
    for (int k = 0; k < NCH; k++) {
        if (k) gridbar();                       // prev chunk's Ihist + A_old stores visible
        if (wid < 4) {
            if (k == 0) chunkB<1>(k, b, wid, lane, S, I, R, dtv, beta, gamma, cwS, smemI, out);
            else        chunkB<0>(k, b, wid, lane, S, I, R, dtv, beta, gamma, cwS, smemI, out);
        } else if (k >= 1 && k < NCH - 1) {
            do_A_old(k + 1, W, lane, cwS);      // history m < 64k for chunk k+1
        }
    }
}

// ================= launch: ONE graph node =================
extern "C" void kernel_launch(void* const* d_in, const int* in_sizes, int n_in,
                              void* d_out, int out_size) {
    const float* t    = (const float*)d_in[0];
    const float* y    = (const float*)d_in[1];
    const float* w1   = (const float*)d_in[2];
    const float* b1   = (const float*)d_in[3];
    const float* w2   = (const float*)d_in[4];
    const float* b2   = (const float*)d_in[5];
    const float* w3   = (const float*)d_in[6];
    const float* b3   = (const float*)d_in[7];
    const float* w4   = (const float*)d_in[8];
    const float* b4   = (const float*)d_in[9];
    const float* beta = (const float*)d_in[10];
    const float* gamma= (const float*)d_in[11];
    float* out = (float*)d_out;

    mega<<<NB, 256>>>(t, y, w1, b1, w2, b2, w3, b3, w4, b4, beta, gamma, out);
}